// round 1
// baseline (speedup 1.0000x reference)
#include <cuda_runtime.h>

// Problem constants
#define Hc   128
#define Wc   128
#define Cc   64
#define Bc   8
#define COUTc 64
#define K2c  9

// Scratch: x transposed to NHWC, weight transposed to [k][c][o]
__device__ float g_xh[Bc * Hc * Wc * Cc];      // [b][y][x][c]  (33.5 MB)
__device__ float g_wt[K2c * Cc * COUTc];       // [k][c][o]

// ---------------------------------------------------------------------------
// Kernel 1: NCHW -> NHWC transpose of x. Block handles (b, h, 32-wide w tile),
// all 64 channels. Coalesced read along w, coalesced write along c.
// ---------------------------------------------------------------------------
__global__ void transpose_x_kernel(const float* __restrict__ x) {
    __shared__ float t[64][33];
    int blk = blockIdx.x;
    int wt  = blk & 3;            // which 32-wide w tile
    int h   = (blk >> 2) & 127;
    int b   = blk >> 9;
    int w0  = wt << 5;

    #pragma unroll
    for (int i = 0; i < 8; i++) {
        int idx = i * 256 + threadIdx.x;
        int c = idx >> 5;
        int w = idx & 31;
        t[c][w] = x[(((b * 64 + c) * 128 + h) << 7) + w0 + w];
    }
    __syncthreads();
    #pragma unroll
    for (int i = 0; i < 8; i++) {
        int idx = i * 256 + threadIdx.x;
        int c = idx & 63;
        int w = idx >> 6;
        g_xh[((((b * 128 + h) << 7) + w0 + w) << 6) + c] = t[c][w];
    }
}

// ---------------------------------------------------------------------------
// Kernel 2: weight [o][c][k] -> [k][c][o]
// ---------------------------------------------------------------------------
__global__ void transpose_w_kernel(const float* __restrict__ wsrc) {
    int idx = blockIdx.x * 256 + threadIdx.x;
    if (idx < K2c * Cc * COUTc) {
        int o = idx & 63;
        int c = (idx >> 6) & 63;
        int k = idx >> 12;
        g_wt[idx] = wsrc[(o * 64 + c) * 9 + k];
    }
}

// Packed f32x2 FMA (Blackwell): acc = a*b + acc on two lanes of a 64-bit reg
#define FMA2(acc, a, b) \
    asm("fma.rn.f32x2 %0, %1, %2, %0;" : "+l"(acc) : "l"(a), "l"(b))

// ---------------------------------------------------------------------------
// Kernel 3: main fused DCNv2.
// Grid: B*Ho = 1024 CTAs, one output row (128 px) per CTA, 256 threads.
// Per k (9 iters): stage cols_k[64c][128px] (bilinear-sampled, mask folded into
// the 4 corner weights) + wdup[c][o] (weight duplicated into both f32x2 lanes)
// into smem, then an smem GEMM: acc[8o][4px] += wdup[c][o] * cols[c][px].
// cols is XOR-swizzled (group g' = g ^ ((c>>2)&7)) so staging STS is <=2-way
// conflicted and GEMM LDS.128 reads are conflict-free.
// ---------------------------------------------------------------------------
__global__ __launch_bounds__(256, 2)
void dcn_main_kernel(const float* __restrict__ offset,
                     const float* __restrict__ mask,
                     const float* __restrict__ bias,
                     float* __restrict__ out)
{
    extern __shared__ float smem[];
    float*  cols = smem;                                   // 64*128 floats (32 KB)
    float2* wdup = (float2*)(smem + 8192);                 // 64*64 float2 (32 KB)
    float*  swgt = smem + 8192 + 8192;                     // 4*128 corner weights
    int*    soff = (int*)(smem + 8192 + 8192 + 512);       // 4*128 corner offsets
    // total: 17408 floats = 69632 bytes

    const int tid  = threadIdx.x;
    const int lane = tid & 31;
    const int warp = tid >> 5;
    const int ho   = blockIdx.x & 127;
    const int b    = blockIdx.x >> 7;

    const float* xb = g_xh + (size_t)b * (Hc * Wc * Cc);

    // 8 output channels x 2 pixel-pairs (4 px), packed f32x2 accumulators
    unsigned long long acc[8][2];
    #pragma unroll
    for (int o = 0; o < 8; o++) { acc[o][0] = 0ull; acc[o][1] = 0ull; }

    #pragma unroll 1
    for (int k = 0; k < 9; k++) {
        __syncthreads();  // protect cols/wdup from previous GEMM readers

        // ---- stage duplicated weights for this k ----
        const float* wtk = g_wt + k * (Cc * COUTc);
        #pragma unroll
        for (int i = 0; i < 16; i++) {
            int idx = i * 256 + tid;
            float v = wtk[idx];
            wdup[idx] = make_float2(v, v);
        }

        // ---- per-pixel sample coordinates (threads 0..127) ----
        if (tid < 128) {
            int wo = tid;
            int kr = k / 3, kc = k - kr * 3;
            float dx = offset[(((size_t)b * 18 + 2 * k    ) * 128 + ho) * 128 + wo];
            float dy = offset[(((size_t)b * 18 + 2 * k + 1) * 128 + ho) * 128 + wo];
            float m  = mask  [(((size_t)b * 9  + k        ) * 128 + ho) * 128 + wo];
            float py = (float)(ho - 1 + kr) + dy;
            float px = (float)(wo - 1 + kc) + dx;
            float y0f = floorf(py), x0f = floorf(px);
            float fy = py - y0f, fx = px - x0f;
            float gy = 1.0f - fy, gx = 1.0f - fx;
            float y1f = y0f + 1.0f, x1f = x0f + 1.0f;
            bool vy0 = (y0f >= 0.0f) && (y0f <= 127.0f);
            bool vy1 = (y1f >= 0.0f) && (y1f <= 127.0f);
            bool vx0 = (x0f >= 0.0f) && (x0f <= 127.0f);
            bool vx1 = (x1f >= 0.0f) && (x1f <= 127.0f);
            int iy0 = min(max((int)y0f, 0), 127);
            int iy1 = min(max((int)y1f, 0), 127);
            int ix0 = min(max((int)x0f, 0), 127);
            int ix1 = min(max((int)x1f, 0), 127);
            swgt[wo]       = (vy0 && vx0) ? gy * gx * m : 0.0f;
            swgt[128 + wo] = (vy0 && vx1) ? gy * fx * m : 0.0f;
            swgt[256 + wo] = (vy1 && vx0) ? fy * gx * m : 0.0f;
            swgt[384 + wo] = (vy1 && vx1) ? fy * fx * m : 0.0f;
            soff[wo]       = (iy0 * 128 + ix0) << 6;
            soff[128 + wo] = (iy0 * 128 + ix1) << 6;
            soff[256 + wo] = (iy1 * 128 + ix0) << 6;
            soff[384 + wo] = (iy1 * 128 + ix1) << 6;
        }
        __syncthreads();

        // ---- stage cols_k: 2048 (px, channel-quad) work items ----
        // lanes 0..15 share a pixel (contiguous 256B corner spans -> few
        // L1tex wavefronts); writes are 4 scalar STS with swizzled columns.
        #pragma unroll
        for (int i = 0; i < 8; i++) {
            int sub = i * 256 + tid;
            int cq  = sub & 15;       // channel quad 0..15
            int px  = sub >> 4;       // pixel 0..127
            int cb  = cq << 2;

            float w00 = swgt[px],       w01 = swgt[128 + px];
            float w10 = swgt[256 + px], w11 = swgt[384 + px];

            float4 c00 = *(const float4*)(xb + soff[px]       + cb);
            float4 c01 = *(const float4*)(xb + soff[128 + px] + cb);
            float4 c10 = *(const float4*)(xb + soff[256 + px] + cb);
            float4 c11 = *(const float4*)(xb + soff[384 + px] + cb);

            float vx = c00.x * w00 + c01.x * w01 + c10.x * w10 + c11.x * w11;
            float vy = c00.y * w00 + c01.y * w01 + c10.y * w10 + c11.y * w11;
            float vz = c00.z * w00 + c01.z * w01 + c10.z * w10 + c11.z * w11;
            float vw = c00.w * w00 + c01.w * w01 + c10.w * w10 + c11.w * w11;

            int sg    = (px >> 2) ^ (cq & 7);          // swizzled px-group
            int wbase = (cb << 7) + (sg << 2) + (px & 3);
            cols[wbase]       = vx;
            cols[wbase + 128] = vy;
            cols[wbase + 256] = vz;
            cols[wbase + 384] = vw;
        }
        __syncthreads();

        // ---- GEMM: acc[o][px] += wdup[c][o] * cols[c][px] ----
        const int o0 = warp << 3;
        #pragma unroll 4
        for (int c = 0; c < 64; c++) {
            const ulonglong2* wr = (const ulonglong2*)(wdup + c * 64 + o0);
            ulonglong2 wA = wr[0], wB = wr[1], wC = wr[2], wD = wr[3];
            int col = (lane ^ ((c >> 2) & 7)) << 2;    // un-swizzle this lane's px group
            ulonglong2 cv = *(const ulonglong2*)(cols + (c << 7) + col);
            FMA2(acc[0][0], wA.x, cv.x); FMA2(acc[0][1], wA.x, cv.y);
            FMA2(acc[1][0], wA.y, cv.x); FMA2(acc[1][1], wA.y, cv.y);
            FMA2(acc[2][0], wB.x, cv.x); FMA2(acc[2][1], wB.x, cv.y);
            FMA2(acc[3][0], wB.y, cv.x); FMA2(acc[3][1], wB.y, cv.y);
            FMA2(acc[4][0], wC.x, cv.x); FMA2(acc[4][1], wC.x, cv.y);
            FMA2(acc[5][0], wC.y, cv.x); FMA2(acc[5][1], wC.y, cv.y);
            FMA2(acc[6][0], wD.x, cv.x); FMA2(acc[6][1], wD.x, cv.y);
            FMA2(acc[7][0], wD.y, cv.x); FMA2(acc[7][1], wD.y, cv.y);
        }
    }

    // ---- epilogue: add bias, write NCHW fp32 output ----
    const int o0  = warp << 3;
    const int px0 = lane << 2;
    #pragma unroll
    for (int o = 0; o < 8; o++) {
        union { unsigned long long u; float2 f; } a0, a1;
        a0.u = acc[o][0];
        a1.u = acc[o][1];
        float bv = bias[o0 + o];
        float4 r = make_float4(a0.f.x + bv, a0.f.y + bv, a1.f.x + bv, a1.f.y + bv);
        *(float4*)(out + ((((size_t)b * COUTc + o0 + o) * Hc + ho) * Wc + px0)) = r;
    }
}

// ---------------------------------------------------------------------------
extern "C" void kernel_launch(void* const* d_in, const int* in_sizes, int n_in,
                              void* d_out, int out_size) {
    const float* x      = (const float*)d_in[0];
    const float* offset = (const float*)d_in[1];
    const float* mask   = (const float*)d_in[2];
    const float* weight = (const float*)d_in[3];
    const float* bias   = (const float*)d_in[4];
    float* out = (float*)d_out;

    cudaFuncSetAttribute(dcn_main_kernel,
                         cudaFuncAttributeMaxDynamicSharedMemorySize, 69632);

    transpose_x_kernel<<<4096, 256>>>(x);
    transpose_w_kernel<<<144, 256>>>(weight);
    dcn_main_kernel<<<1024, 256, 69632>>>(offset, mask, bias, out);
}

// round 2
// speedup vs baseline: 1.0460x; 1.0460x over previous
#include <cuda_runtime.h>

// Problem constants
#define Hc   128
#define Wc   128
#define Cc   64
#define Bc   8
#define COUTc 64
#define K2c  9

// Scratch: x transposed to NHWC, weight transposed to [k][c][o]
__device__ float g_xh[Bc * Hc * Wc * Cc];      // [b][y][x][c]  (33.5 MB)
__device__ float g_wt[K2c * Cc * COUTc];       // [k][c][o]

// ---------------------------------------------------------------------------
// Kernel 1: NCHW -> NHWC transpose of x.
// ---------------------------------------------------------------------------
__global__ void transpose_x_kernel(const float* __restrict__ x) {
    __shared__ float t[64][33];
    int blk = blockIdx.x;
    int wt  = blk & 3;
    int h   = (blk >> 2) & 127;
    int b   = blk >> 9;
    int w0  = wt << 5;

    #pragma unroll
    for (int i = 0; i < 8; i++) {
        int idx = i * 256 + threadIdx.x;
        int c = idx >> 5;
        int w = idx & 31;
        t[c][w] = x[(((b * 64 + c) * 128 + h) << 7) + w0 + w];
    }
    __syncthreads();
    #pragma unroll
    for (int i = 0; i < 8; i++) {
        int idx = i * 256 + threadIdx.x;
        int c = idx & 63;
        int w = idx >> 6;
        g_xh[((((b * 128 + h) << 7) + w0 + w) << 6) + c] = t[c][w];
    }
}

// ---------------------------------------------------------------------------
// Kernel 2: weight [o][c][k] -> [k][c][o]
// ---------------------------------------------------------------------------
__global__ void transpose_w_kernel(const float* __restrict__ wsrc) {
    int idx = blockIdx.x * 256 + threadIdx.x;
    if (idx < K2c * Cc * COUTc) {
        int o = idx & 63;
        int c = (idx >> 6) & 63;
        int k = idx >> 12;
        g_wt[idx] = wsrc[(o * 64 + c) * 9 + k];
    }
}

// Packed f32x2 FMA (Blackwell)
#define FMA2(acc, a, b) \
    asm("fma.rn.f32x2 %0, %1, %2, %0;" : "+l"(acc) : "l"(a), "l"(b))

// ---------------------------------------------------------------------------
// Kernel 3: main fused DCNv2, software-pipelined over the 9 kernel taps.
//
// Grid: B*Ho = 1024 CTAs, one output row (128 px) per CTA, 256 threads,
// 2 CTAs/SM. Double-buffered cols + coords: iteration k stages tap k+1's
// cols and tap k+2's coords while GEMM consumes tap k, so the LDG/L1tex
// staging work is issued a full GEMM phase before its consumption and
// overlaps the FMA-bound GEMM (within CTA via reordering, across the 2
// resident CTAs via phase slip).
//
// smem: cols[2][64c][128px] 64KB | wdup[64c][64o] f32x2 32KB |
//       coords[2][(4*128 wgt + 4*128 off)] 8KB  => 104KB.
// ---------------------------------------------------------------------------
__global__ __launch_bounds__(256, 2)
void dcn_main_kernel(const float* __restrict__ offset,
                     const float* __restrict__ mask,
                     const float* __restrict__ bias,
                     float* __restrict__ out)
{
    extern __shared__ float smem[];
    float*  colsbuf = smem;                                // 2 x 8192 floats
    float2* wdup    = (float2*)(smem + 16384);             // 4096 float2
    float*  cbase   = smem + 16384 + 8192;                 // 2 x 1024 floats

    const int tid  = threadIdx.x;
    const int lane = tid & 31;
    const int warp = tid >> 5;
    const int ho   = blockIdx.x & 127;
    const int b    = blockIdx.x >> 7;

    const float* xb = g_xh + (size_t)b * (Hc * Wc * Cc);

    // ---- coordinate precompute for tap kk into coord buffer (kk&1) ----
    auto coords = [&](int kk) {
        if (tid < 128) {
            float* swgt = cbase + ((kk & 1) << 10);
            int*   soff = (int*)(swgt + 512);
            int wo = tid;
            int kr = kk / 3, kc = kk - kr * 3;
            float dx = offset[(((size_t)b * 18 + 2 * kk    ) * 128 + ho) * 128 + wo];
            float dy = offset[(((size_t)b * 18 + 2 * kk + 1) * 128 + ho) * 128 + wo];
            float m  = mask  [(((size_t)b * 9  + kk        ) * 128 + ho) * 128 + wo];
            float py = (float)(ho - 1 + kr) + dy;
            float px = (float)(wo - 1 + kc) + dx;
            float y0f = floorf(py), x0f = floorf(px);
            float fy = py - y0f, fx = px - x0f;
            float gy = 1.0f - fy, gx = 1.0f - fx;
            float y1f = y0f + 1.0f, x1f = x0f + 1.0f;
            bool vy0 = (y0f >= 0.0f) && (y0f <= 127.0f);
            bool vy1 = (y1f >= 0.0f) && (y1f <= 127.0f);
            bool vx0 = (x0f >= 0.0f) && (x0f <= 127.0f);
            bool vx1 = (x1f >= 0.0f) && (x1f <= 127.0f);
            int iy0 = min(max((int)y0f, 0), 127);
            int iy1 = min(max((int)y1f, 0), 127);
            int ix0 = min(max((int)x0f, 0), 127);
            int ix1 = min(max((int)x1f, 0), 127);
            swgt[wo]       = (vy0 && vx0) ? gy * gx * m : 0.0f;
            swgt[128 + wo] = (vy0 && vx1) ? gy * fx * m : 0.0f;
            swgt[256 + wo] = (vy1 && vx0) ? fy * gx * m : 0.0f;
            swgt[384 + wo] = (vy1 && vx1) ? fy * fx * m : 0.0f;
            soff[wo]       = (iy0 * 128 + ix0) << 6;
            soff[128 + wo] = (iy0 * 128 + ix1) << 6;
            soff[256 + wo] = (iy1 * 128 + ix0) << 6;
            soff[384 + wo] = (iy1 * 128 + ix1) << 6;
        }
    };

    // ---- stage cols for tap kk (reads coord buffer (kk&1), writes cols (kk&1))
    auto stage_cols = [&](int kk) {
        float* cols = colsbuf + ((kk & 1) << 13);
        float* swgt = cbase + ((kk & 1) << 10);
        int*   soff = (int*)(swgt + 512);
        #pragma unroll
        for (int i = 0; i < 8; i++) {
            int sub = i * 256 + tid;
            int cq  = sub & 15;       // channel quad 0..15
            int px  = sub >> 4;       // pixel 0..127
            int cb  = cq << 2;

            float w00 = swgt[px],       w01 = swgt[128 + px];
            float w10 = swgt[256 + px], w11 = swgt[384 + px];

            float4 c00 = *(const float4*)(xb + soff[px]       + cb);
            float4 c01 = *(const float4*)(xb + soff[128 + px] + cb);
            float4 c10 = *(const float4*)(xb + soff[256 + px] + cb);
            float4 c11 = *(const float4*)(xb + soff[384 + px] + cb);

            float vx = c00.x * w00 + c01.x * w01 + c10.x * w10 + c11.x * w11;
            float vy = c00.y * w00 + c01.y * w01 + c10.y * w10 + c11.y * w11;
            float vz = c00.z * w00 + c01.z * w01 + c10.z * w10 + c11.z * w11;
            float vw = c00.w * w00 + c01.w * w01 + c10.w * w10 + c11.w * w11;

            int sg    = (px >> 2) ^ (cq & 7);          // swizzled px-group
            int wbase = (cb << 7) + (sg << 2) + (px & 3);
            cols[wbase]       = vx;
            cols[wbase + 128] = vy;
            cols[wbase + 256] = vz;
            cols[wbase + 384] = vw;
        }
    };

    // 8 output channels x 2 pixel-pairs (4 px), packed f32x2 accumulators
    unsigned long long acc[8][2];
    #pragma unroll
    for (int o = 0; o < 8; o++) { acc[o][0] = 0ull; acc[o][1] = 0ull; }

    // ---- prologue: coords for taps 0 and 1, cols for tap 0 ----
    coords(0);
    coords(1);
    __syncthreads();
    stage_cols(0);

    #pragma unroll 1
    for (int k = 0; k < 9; k++) {
        __syncthreads();   // A: cols[k] visible; GEMM k-1 done with wdup/cols[k+1 buffer]

        // ---- stage duplicated weights for this k (LDG.64 + STS.128) ----
        {
            const float2* wtk2 = (const float2*)(g_wt + k * (Cc * COUTc));
            #pragma unroll
            for (int i = 0; i < 8; i++) {
                int idx = i * 256 + tid;                 // 0..2047 float2 elems
                float2 w2 = wtk2[idx];
                ((float4*)wdup)[idx] = make_float4(w2.x, w2.x, w2.y, w2.y);
            }
        }
        if (k < 8) stage_cols(k + 1);      // heavy LDG work, a full GEMM ahead
        if (k < 7) coords(k + 2);
        __syncthreads();   // B: wdup[k] + cols[k] ready for GEMM

        // ---- GEMM: acc[o][px] += wdup[c][o] * cols[c][px] ----
        const float* cols = colsbuf + ((k & 1) << 13);
        const int o0 = warp << 3;
        #pragma unroll 4
        for (int c = 0; c < 64; c++) {
            const ulonglong2* wr = (const ulonglong2*)(wdup + c * 64 + o0);
            ulonglong2 wA = wr[0], wB = wr[1], wC = wr[2], wD = wr[3];
            int col = (lane ^ ((c >> 2) & 7)) << 2;     // un-swizzle px group
            ulonglong2 cv = *(const ulonglong2*)(cols + (c << 7) + col);
            FMA2(acc[0][0], wA.x, cv.x); FMA2(acc[0][1], wA.x, cv.y);
            FMA2(acc[1][0], wA.y, cv.x); FMA2(acc[1][1], wA.y, cv.y);
            FMA2(acc[2][0], wB.x, cv.x); FMA2(acc[2][1], wB.x, cv.y);
            FMA2(acc[3][0], wB.y, cv.x); FMA2(acc[3][1], wB.y, cv.y);
            FMA2(acc[4][0], wC.x, cv.x); FMA2(acc[4][1], wC.x, cv.y);
            FMA2(acc[5][0], wC.y, cv.x); FMA2(acc[5][1], wC.y, cv.y);
            FMA2(acc[6][0], wD.x, cv.x); FMA2(acc[6][1], wD.x, cv.y);
            FMA2(acc[7][0], wD.y, cv.x); FMA2(acc[7][1], wD.y, cv.y);
        }
    }

    // ---- epilogue: add bias, write NCHW fp32 output ----
    const int o0  = warp << 3;
    const int px0 = lane << 2;
    #pragma unroll
    for (int o = 0; o < 8; o++) {
        union { unsigned long long u; float2 f; } a0, a1;
        a0.u = acc[o][0];
        a1.u = acc[o][1];
        float bv = bias[o0 + o];
        float4 r = make_float4(a0.f.x + bv, a0.f.y + bv, a1.f.x + bv, a1.f.y + bv);
        *(float4*)(out + ((((size_t)b * COUTc + o0 + o) * Hc + ho) * Wc + px0)) = r;
    }
}

// ---------------------------------------------------------------------------
extern "C" void kernel_launch(void* const* d_in, const int* in_sizes, int n_in,
                              void* d_out, int out_size) {
    const float* x      = (const float*)d_in[0];
    const float* offset = (const float*)d_in[1];
    const float* mask   = (const float*)d_in[2];
    const float* weight = (const float*)d_in[3];
    const float* bias   = (const float*)d_in[4];
    float* out = (float*)d_out;

    cudaFuncSetAttribute(dcn_main_kernel,
                         cudaFuncAttributeMaxDynamicSharedMemorySize, 106496);

    transpose_x_kernel<<<4096, 256>>>(x);
    transpose_w_kernel<<<144, 256>>>(weight);
    dcn_main_kernel<<<1024, 256, 106496>>>(offset, mask, bias, out);
}